// round 13
// baseline (speedup 1.0000x reference)
#include <cuda_runtime.h>

#define NC       19
#define N_IMG    8
#define HW       (512 * 1024)
#define VEC      2
#define NGROUPS  (HW / VEC)        // float2 groups per image = 262144
#define BPI      37                // blocks per image -> 296 total = 2/SM x 148
#define THREADS  256
#define NWARPS   (THREADS / 32)

// Exclusive per-block slots (deterministic, no global atomics, no zero-init).
__device__ float        g_partS[(size_t)N_IMG * BPI * NC];
__device__ unsigned int g_partH[(size_t)N_IMG * BPI * NC];

__global__ __launch_bounds__(THREADS, 2)
void iwms_main_kernel(const float* __restrict__ in) {
    const int n    = blockIdx.y;
    const int lane = threadIdx.x & 31;
    const int wid  = threadIdx.x >> 5;

    __shared__ unsigned int sHist[NWARPS][NC];
    __shared__ float        sS[NWARPS][NC];

    if (lane < NC) sHist[wid][lane] = 0u;
    __syncthreads();

    const float* base = in + (size_t)n * NC * HW;

    float acc[NC];
#pragma unroll
    for (int c = 0; c < NC; c++) acc[c] = 0.0f;

    for (int g = blockIdx.x * THREADS + threadIdx.x; g < NGROUPS;
         g += BPI * THREADS) {
        float2 x[NC];
#pragma unroll
        for (int c = 0; c < NC; c++) {
            x[c] = __ldg(reinterpret_cast<const float2*>(base + (size_t)c * HW) + g);
        }

        // max + argmax per pixel (strict > keeps first index, matches jnp.argmax)
        float mx = x[0].x, my = x[0].y;
        int   ax = 0,      ay = 0;
#pragma unroll
        for (int c = 1; c < NC; c++) {
            if (x[c].x > mx) { mx = x[c].x; ax = c; }
            if (x[c].y > my) { my = x[c].y; ay = c; }
        }

        // exponentials + partition function (max folds into the FFMA)
        float Zx = 0.0f, Zy = 0.0f;
#pragma unroll
        for (int c = 0; c < NC; c++) {
            x[c].x = __expf(x[c].x - mx); Zx += x[c].x;
            x[c].y = __expf(x[c].y - my); Zy += x[c].y;
        }
        const float izx = __fdividef(1.0f, Zx);
        const float izy = __fdividef(1.0f, Zy);

#pragma unroll
        for (int c = 0; c < NC; c++) {
            float px = x[c].x * izx;
            float py = x[c].y * izy;
            acc[c] = fmaf(px, px, acc[c]);
            acc[c] = fmaf(py, py, acc[c]);
        }

        atomicAdd(&sHist[wid][ax], 1u);
        atomicAdd(&sHist[wid][ay], 1u);
    }

    // warp shuffle-reduce the 19 class sums
#pragma unroll
    for (int c = 0; c < NC; c++) {
        float v = acc[c];
        v += __shfl_xor_sync(0xffffffffu, v, 16);
        v += __shfl_xor_sync(0xffffffffu, v, 8);
        v += __shfl_xor_sync(0xffffffffu, v, 4);
        v += __shfl_xor_sync(0xffffffffu, v, 2);
        v += __shfl_xor_sync(0xffffffffu, v, 1);
        if (lane == 0) sS[wid][c] = v;
    }
    __syncthreads();

    // cross-warp combine -> exclusive per-block slots (deterministic)
    if (threadIdx.x < NC) {
        float s = 0.0f;
        unsigned int h = 0u;
#pragma unroll
        for (int w = 0; w < NWARPS; w++) {
            s += sS[w][threadIdx.x];
            h += sHist[w][threadIdx.x];
        }
        const size_t slot = ((size_t)n * BPI + blockIdx.x) * NC + threadIdx.x;
        g_partS[slot] = s;
        g_partH[slot] = h;
    }
}

__global__ __launch_bounds__(256)
void iwms_finalize_kernel(float* __restrict__ out) {
    __shared__ float sh[N_IMG * NC];     // histogram with 0 -> 1
    __shared__ float shsum[N_IMG];       // per-image sum AFTER replacement
    __shared__ float sred[256];          // padded tree-reduce buffer

    const int t = threadIdx.x;

    // Phase A: per-(n,c) histogram totals. Unrolled -> 37 independent LDGs in flight.
    if (t < N_IMG * NC) {
        const int n = t / NC;
        const int c = t - n * NC;
        const size_t base = (size_t)n * BPI * NC + c;
        unsigned int h = 0u;
#pragma unroll
        for (int b = 0; b < BPI; b++) h += g_partH[base + (size_t)b * NC];
        sh[t] = (h == 0u) ? 1.0f : (float)h;
    }
    __syncthreads();

    // Phase B: per-image sum of the (zero-replaced) histogram.
    if (t < N_IMG) {
        float s = 0.0f;
#pragma unroll
        for (int c = 0; c < NC; c++) s += sh[t * NC + c];
        shsum[t] = s;
    }
    __syncthreads();

    // Phase C: weighted per-(n,c) terms. Unrolled S-sum + fast powf.
    float term = 0.0f;
    if (t < N_IMG * NC) {
        const int n = t / NC;
        const int c = t - n * NC;
        const size_t base = (size_t)n * BPI * NC + c;
        float s = 0.0f;
#pragma unroll
        for (int b = 0; b < BPI; b++) s += g_partS[base + (size_t)b * NC];
        term = s * __powf(shsum[n] / sh[t], 0.2f);
    }
    sred[t] = term;
    __syncthreads();

    // Phase D: deterministic tree reduction over 256 slots (152 live, rest 0).
#pragma unroll
    for (int stride = 128; stride > 0; stride >>= 1) {
        if (t < stride) sred[t] += sred[t + stride];
        __syncthreads();
    }

    if (t == 0) {
        const float denom = (float)N_IMG * (float)NC * (float)HW;
        out[0] = -sred[0] / denom;
    }
}

extern "C" void kernel_launch(void* const* d_in, const int* in_sizes, int n_in,
                              void* d_out, int out_size) {
    const float* in = (const float*)d_in[0];
    float* out = (float*)d_out;
    (void)in_sizes; (void)n_in; (void)out_size;

    dim3 grid(BPI, N_IMG);
    iwms_main_kernel<<<grid, THREADS>>>(in);
    iwms_finalize_kernel<<<1, 256>>>(out);
}

// round 14
// speedup vs baseline: 1.0279x; 1.0279x over previous
#include <cuda_runtime.h>

#define NC       19
#define N_IMG    8
#define HW       (512 * 1024)
#define VEC      2
#define NGROUPS  (HW / VEC)        // float2 groups per image = 262144
#define BPI      37                // blocks per image -> 296 total = 2/SM x 148
#define THREADS  256
#define NWARPS   (THREADS / 32)
#define NBLOCKS  (BPI * N_IMG)

// Exclusive per-block slots (deterministic, no zero-init needed).
__device__ float        g_partS[(size_t)N_IMG * BPI * NC];
__device__ unsigned int g_partH[(size_t)N_IMG * BPI * NC];
// Last-block-done counter. Self-resetting inside the kernel -> graph-replay safe.
__device__ unsigned int g_done = 0;

__global__ __launch_bounds__(THREADS, 2)
void iwms_fused_kernel(const float* __restrict__ in, float* __restrict__ out) {
    const int n    = blockIdx.y;
    const int lane = threadIdx.x & 31;
    const int wid  = threadIdx.x >> 5;

    __shared__ unsigned int sHist[NWARPS][NC];
    __shared__ float        sS[NWARPS][NC];

    if (lane < NC) sHist[wid][lane] = 0u;
    __syncthreads();

    const float* base = in + (size_t)n * NC * HW;

    float acc[NC];
#pragma unroll
    for (int c = 0; c < NC; c++) acc[c] = 0.0f;

    for (int g = blockIdx.x * THREADS + threadIdx.x; g < NGROUPS;
         g += BPI * THREADS) {
        float2 x[NC];
#pragma unroll
        for (int c = 0; c < NC; c++) {
            x[c] = __ldg(reinterpret_cast<const float2*>(base + (size_t)c * HW) + g);
        }

        // max + argmax per pixel (strict > keeps first index, matches jnp.argmax)
        float mx = x[0].x, my = x[0].y;
        int   ax = 0,      ay = 0;
#pragma unroll
        for (int c = 1; c < NC; c++) {
            if (x[c].x > mx) { mx = x[c].x; ax = c; }
            if (x[c].y > my) { my = x[c].y; ay = c; }
        }

        // exponentials + partition function (max folds into the FFMA)
        float Zx = 0.0f, Zy = 0.0f;
#pragma unroll
        for (int c = 0; c < NC; c++) {
            x[c].x = __expf(x[c].x - mx); Zx += x[c].x;
            x[c].y = __expf(x[c].y - my); Zy += x[c].y;
        }
        const float izx = __fdividef(1.0f, Zx);
        const float izy = __fdividef(1.0f, Zy);

#pragma unroll
        for (int c = 0; c < NC; c++) {
            float px = x[c].x * izx;
            float py = x[c].y * izy;
            acc[c] = fmaf(px, px, acc[c]);
            acc[c] = fmaf(py, py, acc[c]);
        }

        atomicAdd(&sHist[wid][ax], 1u);
        atomicAdd(&sHist[wid][ay], 1u);
    }

    // warp shuffle-reduce the 19 class sums
#pragma unroll
    for (int c = 0; c < NC; c++) {
        float v = acc[c];
        v += __shfl_xor_sync(0xffffffffu, v, 16);
        v += __shfl_xor_sync(0xffffffffu, v, 8);
        v += __shfl_xor_sync(0xffffffffu, v, 4);
        v += __shfl_xor_sync(0xffffffffu, v, 2);
        v += __shfl_xor_sync(0xffffffffu, v, 1);
        if (lane == 0) sS[wid][c] = v;
    }
    __syncthreads();

    // cross-warp combine -> exclusive per-block slots (deterministic)
    if (threadIdx.x < NC) {
        float s = 0.0f;
        unsigned int h = 0u;
#pragma unroll
        for (int w = 0; w < NWARPS; w++) {
            s += sS[w][threadIdx.x];
            h += sHist[w][threadIdx.x];
        }
        const size_t slot = ((size_t)n * BPI + blockIdx.x) * NC + threadIdx.x;
        g_partS[slot] = s;
        g_partH[slot] = h;
    }

    // ---- last-block-done gate ----
    __threadfence();                       // partials visible before counter bump
    __shared__ unsigned int sIsLast;
    __syncthreads();                       // all threads' STG issued before t0 bumps
    if (threadIdx.x == 0) {
        unsigned int prev = atomicAdd(&g_done, 1u);
        sIsLast = (prev == NBLOCKS - 1) ? 1u : 0u;
    }
    __syncthreads();
    if (!sIsLast) return;

    // ---- fused finalize (runs in exactly one block) ----
    if (threadIdx.x == 0) g_done = 0u;     // reset for next graph replay

    __shared__ float sh[N_IMG * NC];       // histogram with 0 -> 1
    __shared__ float shsum[N_IMG];         // per-image sum AFTER replacement
    __shared__ float sred[256];            // padded tree-reduce buffer

    const int t = threadIdx.x;

    // Phase A: per-(n,c) histogram totals (37 independent L2-coherent loads).
    if (t < N_IMG * NC) {
        const int nn = t / NC;
        const int c  = t - nn * NC;
        const size_t b0 = (size_t)nn * BPI * NC + c;
        unsigned int h = 0u;
#pragma unroll
        for (int b = 0; b < BPI; b++) h += __ldcg(&g_partH[b0 + (size_t)b * NC]);
        sh[t] = (h == 0u) ? 1.0f : (float)h;
    }
    __syncthreads();

    // Phase B: per-image sum of the (zero-replaced) histogram.
    if (t < N_IMG) {
        float s = 0.0f;
#pragma unroll
        for (int c = 0; c < NC; c++) s += sh[t * NC + c];
        shsum[t] = s;
    }
    __syncthreads();

    // Phase C: weighted per-(n,c) terms.
    float term = 0.0f;
    if (t < N_IMG * NC) {
        const int nn = t / NC;
        const size_t b0 = (size_t)nn * BPI * NC + (t - nn * NC);
        float s = 0.0f;
#pragma unroll
        for (int b = 0; b < BPI; b++) s += __ldcg(&g_partS[b0 + (size_t)b * NC]);
        term = s * __powf(shsum[nn] / sh[t], 0.2f);
    }
    sred[t] = term;
    __syncthreads();

    // Phase D: deterministic tree reduction over 256 slots (152 live, rest 0).
#pragma unroll
    for (int stride = 128; stride > 0; stride >>= 1) {
        if (t < stride) sred[t] += sred[t + stride];
        __syncthreads();
    }

    if (t == 0) {
        const float denom = (float)N_IMG * (float)NC * (float)HW;
        out[0] = -sred[0] / denom;
    }
}

extern "C" void kernel_launch(void* const* d_in, const int* in_sizes, int n_in,
                              void* d_out, int out_size) {
    const float* in = (const float*)d_in[0];
    float* out = (float*)d_out;
    (void)in_sizes; (void)n_in; (void)out_size;

    dim3 grid(BPI, N_IMG);
    iwms_fused_kernel<<<grid, THREADS>>>(in, out);
}

// round 15
// speedup vs baseline: 1.1411x; 1.1101x over previous
#include <cuda_runtime.h>

#define NC       19
#define N_IMG    8
#define HW       (512 * 1024)
#define VEC      2
#define NGROUPS  (HW / VEC)        // float2 groups per image = 262144
#define BPI      55                // 8*55 = 440 blocks -> 3 CTAs/SM single wave (444 cap)
#define THREADS  256
#define NWARPS   (THREADS / 32)
#define NBLOCKS  (BPI * N_IMG)

// Exclusive per-block slots (deterministic, no zero-init needed).
__device__ float        g_partS[(size_t)N_IMG * BPI * NC];
__device__ unsigned int g_partH[(size_t)N_IMG * BPI * NC];
// Last-block-done counter. Self-resetting inside the kernel -> graph-replay safe.
__device__ unsigned int g_done = 0;

__global__ __launch_bounds__(THREADS, 3)
void iwms_fused_kernel(const float* __restrict__ in, float* __restrict__ out) {
    const int n    = blockIdx.y;
    const int lane = threadIdx.x & 31;
    const int wid  = threadIdx.x >> 5;

    __shared__ unsigned int sHist[NWARPS][NC];
    __shared__ float        sS[NWARPS][NC];

    if (lane < NC) sHist[wid][lane] = 0u;
    __syncthreads();

    const float* base = in + (size_t)n * NC * HW;

    float acc[NC];
#pragma unroll
    for (int c = 0; c < NC; c++) acc[c] = 0.0f;

    for (int g = blockIdx.x * THREADS + threadIdx.x; g < NGROUPS;
         g += BPI * THREADS) {
        float2 x[NC];
#pragma unroll
        for (int c = 0; c < NC; c++) {
            // streaming load: 318 MB, zero reuse -> don't pollute L2
            x[c] = __ldcs(reinterpret_cast<const float2*>(base + (size_t)c * HW) + g);
        }

        // max + argmax per pixel (strict > keeps first index, matches jnp.argmax)
        float mx = x[0].x, my = x[0].y;
        int   ax = 0,      ay = 0;
#pragma unroll
        for (int c = 1; c < NC; c++) {
            if (x[c].x > mx) { mx = x[c].x; ax = c; }
            if (x[c].y > my) { my = x[c].y; ay = c; }
        }

        // exponentials + partition function (max folds into the FFMA)
        float Zx = 0.0f, Zy = 0.0f;
#pragma unroll
        for (int c = 0; c < NC; c++) {
            x[c].x = __expf(x[c].x - mx); Zx += x[c].x;
            x[c].y = __expf(x[c].y - my); Zy += x[c].y;
        }
        const float izx = __fdividef(1.0f, Zx);
        const float izy = __fdividef(1.0f, Zy);

#pragma unroll
        for (int c = 0; c < NC; c++) {
            float px = x[c].x * izx;
            float py = x[c].y * izy;
            acc[c] = fmaf(px, px, acc[c]);
            acc[c] = fmaf(py, py, acc[c]);
        }

        atomicAdd(&sHist[wid][ax], 1u);
        atomicAdd(&sHist[wid][ay], 1u);
    }

    // warp shuffle-reduce the 19 class sums
#pragma unroll
    for (int c = 0; c < NC; c++) {
        float v = acc[c];
        v += __shfl_xor_sync(0xffffffffu, v, 16);
        v += __shfl_xor_sync(0xffffffffu, v, 8);
        v += __shfl_xor_sync(0xffffffffu, v, 4);
        v += __shfl_xor_sync(0xffffffffu, v, 2);
        v += __shfl_xor_sync(0xffffffffu, v, 1);
        if (lane == 0) sS[wid][c] = v;
    }
    __syncthreads();

    // cross-warp combine -> exclusive per-block slots (deterministic)
    if (threadIdx.x < NC) {
        float s = 0.0f;
        unsigned int h = 0u;
#pragma unroll
        for (int w = 0; w < NWARPS; w++) {
            s += sS[w][threadIdx.x];
            h += sHist[w][threadIdx.x];
        }
        const size_t slot = ((size_t)n * BPI + blockIdx.x) * NC + threadIdx.x;
        g_partS[slot] = s;
        g_partH[slot] = h;
    }

    // ---- last-block-done gate ----
    __threadfence();                       // partials visible before counter bump
    __shared__ unsigned int sIsLast;
    __syncthreads();                       // all threads' STG issued before t0 bumps
    if (threadIdx.x == 0) {
        unsigned int prev = atomicAdd(&g_done, 1u);
        sIsLast = (prev == NBLOCKS - 1) ? 1u : 0u;
    }
    __syncthreads();
    if (!sIsLast) return;

    // ---- fused finalize (runs in exactly one block) ----
    if (threadIdx.x == 0) g_done = 0u;     // reset for next graph replay

    __shared__ float sh[N_IMG * NC];       // histogram with 0 -> 1
    __shared__ float shsum[N_IMG];         // per-image sum AFTER replacement
    __shared__ float sred[256];            // padded tree-reduce buffer

    const int t = threadIdx.x;

    // Phase A: per-(n,c) histogram totals (independent L2-coherent loads).
    if (t < N_IMG * NC) {
        const int nn = t / NC;
        const int c  = t - nn * NC;
        const size_t b0 = (size_t)nn * BPI * NC + c;
        unsigned int h = 0u;
#pragma unroll
        for (int b = 0; b < BPI; b++) h += __ldcg(&g_partH[b0 + (size_t)b * NC]);
        sh[t] = (h == 0u) ? 1.0f : (float)h;
    }
    __syncthreads();

    // Phase B: per-image sum of the (zero-replaced) histogram.
    if (t < N_IMG) {
        float s = 0.0f;
#pragma unroll
        for (int c = 0; c < NC; c++) s += sh[t * NC + c];
        shsum[t] = s;
    }
    __syncthreads();

    // Phase C: weighted per-(n,c) terms.
    float term = 0.0f;
    if (t < N_IMG * NC) {
        const int nn = t / NC;
        const size_t b0 = (size_t)nn * BPI * NC + (t - nn * NC);
        float s = 0.0f;
#pragma unroll
        for (int b = 0; b < BPI; b++) s += __ldcg(&g_partS[b0 + (size_t)b * NC]);
        term = s * __powf(shsum[nn] / sh[t], 0.2f);
    }
    sred[t] = term;
    __syncthreads();

    // Phase D: deterministic tree reduction over 256 slots (152 live, rest 0).
#pragma unroll
    for (int stride = 128; stride > 0; stride >>= 1) {
        if (t < stride) sred[t] += sred[t + stride];
        __syncthreads();
    }

    if (t == 0) {
        const float denom = (float)N_IMG * (float)NC * (float)HW;
        out[0] = -sred[0] / denom;
    }
}

extern "C" void kernel_launch(void* const* d_in, const int* in_sizes, int n_in,
                              void* d_out, int out_size) {
    const float* in = (const float*)d_in[0];
    float* out = (float*)d_out;
    (void)in_sizes; (void)n_in; (void)out_size;

    dim3 grid(BPI, N_IMG);
    iwms_fused_kernel<<<grid, THREADS>>>(in, out);
}

// round 16
// speedup vs baseline: 1.1417x; 1.0006x over previous
#include <cuda_runtime.h>

#define NC       19
#define N_IMG    8
#define HW       (512 * 1024)
#define VEC      4
#define NGROUPS  (HW / VEC)        // float4 groups per image = 131072
#define BPI      37                // 8*37 = 296 blocks -> 2 CTAs/SM single wave
#define THREADS  256
#define NWARPS   (THREADS / 32)
#define NBLOCKS  (BPI * N_IMG)
#define LOG2E    1.4426950408889634f

// Exclusive per-block slots (deterministic, no zero-init needed).
__device__ float        g_partS[(size_t)N_IMG * BPI * NC];
__device__ unsigned int g_partH[(size_t)N_IMG * BPI * NC];
// Last-block-done counter. Self-resetting inside the kernel -> graph-replay safe.
__device__ unsigned int g_done = 0;

__device__ __forceinline__ float ex2f(float a) {
    float r;
    asm("ex2.approx.f32 %0, %1;" : "=f"(r) : "f"(a));
    return r;
}

__global__ __launch_bounds__(THREADS, 2)
void iwms_fused_kernel(const float* __restrict__ in, float* __restrict__ out) {
    const int n    = blockIdx.y;
    const int lane = threadIdx.x & 31;
    const int wid  = threadIdx.x >> 5;

    __shared__ unsigned int sHist[NWARPS][NC];
    __shared__ float        sS[NWARPS][NC];

    if (lane < NC) sHist[wid][lane] = 0u;
    __syncthreads();

    const float* base = in + (size_t)n * NC * HW;

    float acc[NC];
#pragma unroll
    for (int c = 0; c < NC; c++) acc[c] = 0.0f;

    for (int g = blockIdx.x * THREADS + threadIdx.x; g < NGROUPS;
         g += BPI * THREADS) {
        float4 x[NC];
#pragma unroll
        for (int c = 0; c < NC; c++) {
            // streaming load: 318 MB, zero reuse -> don't pollute L2
            x[c] = __ldcs(reinterpret_cast<const float4*>(base + (size_t)c * HW) + g);
        }

        // max + argmax per pixel (strict > keeps first index, matches jnp.argmax)
        float mx = x[0].x, my = x[0].y, mz = x[0].z, mw = x[0].w;
        int   ax = 0,      ay = 0,      az = 0,      aw = 0;
#pragma unroll
        for (int c = 1; c < NC; c++) {
            if (x[c].x > mx) { mx = x[c].x; ax = c; }
            if (x[c].y > my) { my = x[c].y; ay = c; }
            if (x[c].z > mz) { mz = x[c].z; az = c; }
            if (x[c].w > mw) { mw = x[c].w; aw = c; }
        }

        // softmax exp: one FFMA + one MUFU.EX2 per element
        const float bx = -mx * LOG2E, by = -my * LOG2E,
                    bz = -mz * LOG2E, bw = -mw * LOG2E;
        float Zx = 0.0f, Zy = 0.0f, Zz = 0.0f, Zw = 0.0f;
#pragma unroll
        for (int c = 0; c < NC; c++) {
            x[c].x = ex2f(fmaf(x[c].x, LOG2E, bx)); Zx += x[c].x;
            x[c].y = ex2f(fmaf(x[c].y, LOG2E, by)); Zy += x[c].y;
            x[c].z = ex2f(fmaf(x[c].z, LOG2E, bz)); Zz += x[c].z;
            x[c].w = ex2f(fmaf(x[c].w, LOG2E, bw)); Zw += x[c].w;
        }
        const float izx = __fdividef(1.0f, Zx);
        const float izy = __fdividef(1.0f, Zy);
        const float izz = __fdividef(1.0f, Zz);
        const float izw = __fdividef(1.0f, Zw);

#pragma unroll
        for (int c = 0; c < NC; c++) {
            float px = x[c].x * izx;
            float py = x[c].y * izy;
            float pz = x[c].z * izz;
            float pw = x[c].w * izw;
            acc[c] = fmaf(px, px, acc[c]);
            acc[c] = fmaf(py, py, acc[c]);
            acc[c] = fmaf(pz, pz, acc[c]);
            acc[c] = fmaf(pw, pw, acc[c]);
        }

        atomicAdd(&sHist[wid][ax], 1u);
        atomicAdd(&sHist[wid][ay], 1u);
        atomicAdd(&sHist[wid][az], 1u);
        atomicAdd(&sHist[wid][aw], 1u);
    }

    // warp shuffle-reduce the 19 class sums
#pragma unroll
    for (int c = 0; c < NC; c++) {
        float v = acc[c];
        v += __shfl_xor_sync(0xffffffffu, v, 16);
        v += __shfl_xor_sync(0xffffffffu, v, 8);
        v += __shfl_xor_sync(0xffffffffu, v, 4);
        v += __shfl_xor_sync(0xffffffffu, v, 2);
        v += __shfl_xor_sync(0xffffffffu, v, 1);
        if (lane == 0) sS[wid][c] = v;
    }
    __syncthreads();

    // cross-warp combine -> exclusive per-block slots (deterministic)
    if (threadIdx.x < NC) {
        float s = 0.0f;
        unsigned int h = 0u;
#pragma unroll
        for (int w = 0; w < NWARPS; w++) {
            s += sS[w][threadIdx.x];
            h += sHist[w][threadIdx.x];
        }
        const size_t slot = ((size_t)n * BPI + blockIdx.x) * NC + threadIdx.x;
        g_partS[slot] = s;
        g_partH[slot] = h;
    }

    // ---- last-block-done gate ----
    __threadfence();                       // partials visible before counter bump
    __shared__ unsigned int sIsLast;
    __syncthreads();                       // all threads' STG issued before t0 bumps
    if (threadIdx.x == 0) {
        unsigned int prev = atomicAdd(&g_done, 1u);
        sIsLast = (prev == NBLOCKS - 1) ? 1u : 0u;
    }
    __syncthreads();
    if (!sIsLast) return;

    // ---- fused finalize (runs in exactly one block) ----
    if (threadIdx.x == 0) g_done = 0u;     // reset for next graph replay

    __shared__ float sh[N_IMG * NC];       // histogram with 0 -> 1
    __shared__ float shsum[N_IMG];         // per-image sum AFTER replacement
    __shared__ float sred[256];            // padded tree-reduce buffer

    const int t = threadIdx.x;

    // Phase A: per-(n,c) histogram totals (independent L2-coherent loads).
    if (t < N_IMG * NC) {
        const int nn = t / NC;
        const int c  = t - nn * NC;
        const size_t b0 = (size_t)nn * BPI * NC + c;
        unsigned int h = 0u;
#pragma unroll
        for (int b = 0; b < BPI; b++) h += __ldcg(&g_partH[b0 + (size_t)b * NC]);
        sh[t] = (h == 0u) ? 1.0f : (float)h;
    }
    __syncthreads();

    // Phase B: per-image sum of the (zero-replaced) histogram.
    if (t < N_IMG) {
        float s = 0.0f;
#pragma unroll
        for (int c = 0; c < NC; c++) s += sh[t * NC + c];
        shsum[t] = s;
    }
    __syncthreads();

    // Phase C: weighted per-(n,c) terms.
    float term = 0.0f;
    if (t < N_IMG * NC) {
        const int nn = t / NC;
        const size_t b0 = (size_t)nn * BPI * NC + (t - nn * NC);
        float s = 0.0f;
#pragma unroll
        for (int b = 0; b < BPI; b++) s += __ldcg(&g_partS[b0 + (size_t)b * NC]);
        term = s * __powf(shsum[nn] / sh[t], 0.2f);
    }
    sred[t] = term;
    __syncthreads();

    // Phase D: deterministic tree reduction over 256 slots (152 live, rest 0).
#pragma unroll
    for (int stride = 128; stride > 0; stride >>= 1) {
        if (t < stride) sred[t] += sred[t + stride];
        __syncthreads();
    }

    if (t == 0) {
        const float denom = (float)N_IMG * (float)NC * (float)HW;
        out[0] = -sred[0] / denom;
    }
}

extern "C" void kernel_launch(void* const* d_in, const int* in_sizes, int n_in,
                              void* d_out, int out_size) {
    const float* in = (const float*)d_in[0];
    float* out = (float*)d_out;
    (void)in_sizes; (void)n_in; (void)out_size;

    dim3 grid(BPI, N_IMG);
    iwms_fused_kernel<<<grid, THREADS>>>(in, out);
}